// round 1
// baseline (speedup 1.0000x reference)
#include <cuda_runtime.h>
#include <cuda_bf16.h>

#define NUM_CLASSES 10

// One CTA per batch. 192 threads = 3 channels * 8 rows * 8 cols.
// Each thread loads one float from the top-left 8x8 patch of its channel,
// block-reduces to the mean, and thread 0 writes the 10 logits.
__global__ __launch_bounds__(192, 8)
void ldc_kernel(const float* __restrict__ x, float* __restrict__ out) {
    const int b   = blockIdx.x;      // batch 0..63
    const int tid = threadIdx.x;     // 0..191

    // tid -> (c, r, col): c = tid/64, within-patch = tid%64, r = w/8, col = w%8
    const int c   = tid >> 6;
    const int w   = tid & 63;
    const int r   = w >> 3;
    const int col = w & 7;

    // x layout: [64, 3, 512, 512] row-major
    const long long idx = (((long long)b * 3 + c) * 512 + r) * 512 + col;
    float v = x[idx];

    // Warp reduce (6 warps of 32)
    #pragma unroll
    for (int off = 16; off > 0; off >>= 1)
        v += __shfl_down_sync(0xFFFFFFFFu, v, off);

    __shared__ float partial[6];
    const int warp = tid >> 5;
    const int lane = tid & 31;
    if (lane == 0) partial[warp] = v;
    __syncthreads();

    if (tid == 0) {
        float total = partial[0] + partial[1] + partial[2]
                    + partial[3] + partial[4] + partial[5];
        float mean = total / 192.0f;
        // Python: int() truncates toward zero; % with positive modulus is non-negative.
        int t = (int)truncf(mean * 10.0f);
        int pred = t % NUM_CLASSES;
        if (pred < 0) pred += NUM_CLASSES;

        float* o = out + b * NUM_CLASSES;
        #pragma unroll
        for (int k = 0; k < NUM_CLASSES; ++k)
            o[k] = (k == pred) ? 10.0f : 0.0f;
    }
}

extern "C" void kernel_launch(void* const* d_in, const int* in_sizes, int n_in,
                              void* d_out, int out_size) {
    const float* x = (const float*)d_in[0];
    float* out = (float*)d_out;
    ldc_kernel<<<64, 192>>>(x, out);
}